// round 7
// baseline (speedup 1.0000x reference)
#include <cuda_runtime.h>

#define B_   8
#define N_   50000
#define CIN  32
#define L_   9
#define K_   288
#define CO   64
#define M_   12500
#define NNZ_ 37500
#define R_   (B_ * N_)          // 400000
#define TILE_R 128
#define GS_S 129                // padded stride: conflict-free transpose STS + scalar LDS

typedef unsigned long long u64;

// fma.rn.f32x2: d.lo += a.lo*b.lo, d.hi += a.hi*b.hi  (packed, 2x FFMA throughput)
#define FMA2(d, a, b) \
    asm("fma.rn.f32x2 %0, %1, %2, %0;" : "+l"(d) : "l"(a), "l"(b))
// Duplicate one f32 into both lanes of a b64.
#define DUP2(d, s) \
    asm("mov.b64 %0, {%1, %1};" : "=l"(d) : "r"(__float_as_uint(s)))
#define UNPACK2(lo, hi, s) \
    asm("mov.b64 {%0, %1}, %2;" : "=f"(lo), "=f"(hi) : "l"(s))

// Intermediate elu(g @ W + b): (B, N, CO) fp32 = 102.4 MB device scratch.
__device__ float g_mid[(size_t)R_ * CO];

// ---------------------------------------------------------------------------
// Kernel 1: gather + GEMM + bias + ELU. 128 threads -> 128x64 tile.
// Thread t: rows ri+16*i (ri=t&15, i=0..7), cols c0..c0+7 (c0=(t>>4)*8),
// accumulated as 8 rows x 4 column-pairs in f32x2 registers.
// ---------------------------------------------------------------------------
__global__ __launch_bounds__(128, 4)
void spiral_gemm_kernel(const float* __restrict__ x,
                        const float* __restrict__ w,
                        const float* __restrict__ bias,
                        const int* __restrict__ sp)
{
    __shared__ float gs[CIN][GS_S];        // transposed g chunk: gs[k][row]
    __shared__ float ws[CIN][CO];          // W chunk
    __shared__ int   goffs[TILE_R][L_];    // (b*N + sp[n,l]) in float4 units

    const int tid = threadIdx.x;
    const int r0  = blockIdx.x * TILE_R;

    for (int i = tid; i < TILE_R * L_; i += 128) {
        int row = i / L_;
        int l   = i - row * L_;
        int rr  = r0 + row;
        int b   = rr / N_;
        int n   = rr - b * N_;
        int idx = sp[n * L_ + l];
        goffs[row][l] = (b * N_ + idx) * (CIN / 4);
    }

    const int ri = tid & 15;
    const int c0 = (tid >> 4) * 8;

    u64 acc[8][4];
#pragma unroll
    for (int i = 0; i < 8; i++)
#pragma unroll
        for (int j = 0; j < 4; j++) acc[i][j] = 0ull;

    const float4* xv = (const float4*)x;
    const float4* wv = (const float4*)w;

    for (int l = 0; l < L_; ++l) {
        __syncthreads();   // previous chunk's compute done before overwrite

        // Stage g chunk: 128 rows x 32 floats, transposed, conflict-free.
#pragma unroll
        for (int it = 0; it < 8; ++it) {
            int i   = tid + it * 128;
            int row = i >> 3;
            int j   = i & 7;
            float4 v = xv[goffs[row][l] + j];
            gs[j * 4 + 0][row] = v.x;
            gs[j * 4 + 1][row] = v.y;
            gs[j * 4 + 2][row] = v.z;
            gs[j * 4 + 3][row] = v.w;
        }
        // Stage W chunk: rows l*32 .. l*32+31, all 64 cols.
#pragma unroll
        for (int it = 0; it < 4; ++it) {
            int i   = tid + it * 128;
            int row = i >> 4;
            int c4  = i & 15;
            ((float4*)&ws[row][0])[c4] = wv[(l * CIN + row) * (CO / 4) + c4];
        }
        __syncthreads();

#pragma unroll 2
        for (int k = 0; k < CIN; ++k) {
            // a values for this k, duplicated into both f32x2 lanes.
            u64 ad[8];
#pragma unroll
            for (int i = 0; i < 8; i++) {
                float a = gs[k][ri + 16 * i];
                DUP2(ad[i], a);
            }
            // W column pairs: two LDS.128, registers reinterpreted as b64 pairs.
            ulonglong2 wq0 = *(const ulonglong2*)&ws[k][c0];
            ulonglong2 wq1 = *(const ulonglong2*)&ws[k][c0 + 4];
            u64 wp0 = wq0.x, wp1 = wq0.y, wp2 = wq1.x, wp3 = wq1.y;
#pragma unroll
            for (int i = 0; i < 8; i++) {
                FMA2(acc[i][0], ad[i], wp0);
                FMA2(acc[i][1], ad[i], wp1);
                FMA2(acc[i][2], ad[i], wp2);
                FMA2(acc[i][3], ad[i], wp3);
            }
        }
    }

    // Epilogue: bias + ELU, store to scratch.
    float bb[8];
#pragma unroll
    for (int j = 0; j < 8; j++) bb[j] = bias[c0 + j];

#pragma unroll
    for (int i = 0; i < 8; i++) {
        int rr = r0 + ri + 16 * i;
        float o[8];
#pragma unroll
        for (int j = 0; j < 4; j++) {
            float lo, hi;
            UNPACK2(lo, hi, acc[i][j]);
            float v0 = lo + bb[2 * j];
            float v1 = hi + bb[2 * j + 1];
            o[2 * j]     = v0 > 0.f ? v0 : expm1f(v0);
            o[2 * j + 1] = v1 > 0.f ? v1 : expm1f(v1);
        }
        float4* dst = (float4*)&g_mid[(size_t)rr * CO + c0];
        dst[0] = make_float4(o[0], o[1], o[2], o[3]);
        dst[1] = make_float4(o[4], o[5], o[6], o[7]);
    }
}

// ---------------------------------------------------------------------------
// Kernel 2: zero the output (harness poisons d_out).
// ---------------------------------------------------------------------------
__global__ void zero_kernel(float4* __restrict__ out)
{
    int i = blockIdx.x * blockDim.x + threadIdx.x;
    out[i] = make_float4(0.f, 0.f, 0.f, 0.f);
}

// ---------------------------------------------------------------------------
// Kernel 3: sparse pooling scatter (coalesced reads + coalesced atomics).
// ---------------------------------------------------------------------------
__global__ void scatter_kernel(const float* __restrict__ values,
                               const int* __restrict__ rows,
                               const int* __restrict__ cols,
                               float* __restrict__ pooled)
{
    int t = blockIdx.x * blockDim.x + threadIdx.x;
    int o = t & 63;
    int b = (t >> 6) & 7;
    int e = t >> 9;
    int col = cols[e];
    int row = rows[e];
    float v = values[e];
    float val = g_mid[((size_t)b * N_ + col) * CO + o];
    atomicAdd(&pooled[((size_t)b * M_ + row) * CO + o], val * v);
}

// ---------------------------------------------------------------------------
// Inputs: 0 x, 1 weight, 2 bias, 3 values, 4 spiral_indices(i32),
//         5 rows(i32), 6 cols(i32), 7 num_out_verts (unused).
// Output: (8, 12500, 64) fp32.
// ---------------------------------------------------------------------------
extern "C" void kernel_launch(void* const* d_in, const int* in_sizes, int n_in,
                              void* d_out, int out_size)
{
    const float* x      = (const float*)d_in[0];
    const float* w      = (const float*)d_in[1];
    const float* bias   = (const float*)d_in[2];
    const float* values = (const float*)d_in[3];
    const int*   sp     = (const int*)d_in[4];
    const int*   rows   = (const int*)d_in[5];
    const int*   cols   = (const int*)d_in[6];
    float*       out    = (float*)d_out;

    spiral_gemm_kernel<<<R_ / TILE_R, 128>>>(x, w, bias, sp);
    zero_kernel<<<(B_ * M_ * CO / 4) / 256, 256>>>((float4*)out);
    scatter_kernel<<<(NNZ_ * 512) / 256, 256>>>(values, rows, cols, out);
}

// round 8
// speedup vs baseline: 1.0076x; 1.0076x over previous
#include <cuda_runtime.h>

#define B_   8
#define N_   50000
#define CIN  32
#define L_   9
#define K_   288
#define CO   64
#define M_   12500
#define NNZ_ 37500
#define R_   (B_ * N_)          // 400000
#define TILE_R 128
#define GS_S 129                // padded stride: conflict-free transpose STS + scalar LDS

typedef unsigned long long u64;

// fma.rn.f32x2: d.lo += a.lo*b.lo, d.hi += a.hi*b.hi  (packed, 2x FFMA throughput)
#define FMA2(d, a, b) \
    asm("fma.rn.f32x2 %0, %1, %2, %0;" : "+l"(d) : "l"(a), "l"(b))
// Duplicate one f32 into both lanes of a b64.
#define DUP2(d, s) \
    asm("mov.b64 %0, {%1, %1};" : "=l"(d) : "r"(__float_as_uint(s)))
#define UNPACK2(lo, hi, s) \
    asm("mov.b64 {%0, %1}, %2;" : "=f"(lo), "=f"(hi) : "l"(s))

// Intermediate elu(g @ W + b): (B, N, CO) fp32 = 102.4 MB device scratch.
__device__ float g_mid[(size_t)R_ * CO];

// ---------------------------------------------------------------------------
// Kernel 1: gather + GEMM + bias + ELU. 128 threads -> 128x64 tile.
// Thread t: rows ri+16*i (ri=t&15, i=0..7), cols c0..c0+7 (c0=(t>>4)*8),
// accumulated as 8 rows x 4 column-pairs in f32x2 registers.
// ---------------------------------------------------------------------------
__global__ __launch_bounds__(128, 4)
void spiral_gemm_kernel(const float* __restrict__ x,
                        const float* __restrict__ w,
                        const float* __restrict__ bias,
                        const int* __restrict__ sp)
{
    __shared__ float gs[CIN][GS_S];        // transposed g chunk: gs[k][row]
    __shared__ float ws[CIN][CO];          // W chunk
    __shared__ int   goffs[TILE_R][L_];    // (b*N + sp[n,l]) in float4 units

    const int tid = threadIdx.x;
    const int r0  = blockIdx.x * TILE_R;

    for (int i = tid; i < TILE_R * L_; i += 128) {
        int row = i / L_;
        int l   = i - row * L_;
        int rr  = r0 + row;
        int b   = rr / N_;
        int n   = rr - b * N_;
        int idx = sp[n * L_ + l];
        goffs[row][l] = (b * N_ + idx) * (CIN / 4);
    }

    const int ri = tid & 15;
    const int c0 = (tid >> 4) * 8;

    u64 acc[8][4];
#pragma unroll
    for (int i = 0; i < 8; i++)
#pragma unroll
        for (int j = 0; j < 4; j++) acc[i][j] = 0ull;

    const float4* xv = (const float4*)x;
    const float4* wv = (const float4*)w;

    for (int l = 0; l < L_; ++l) {
        __syncthreads();   // previous chunk's compute done before overwrite

        // Stage g chunk: 128 rows x 32 floats, transposed, conflict-free.
#pragma unroll
        for (int it = 0; it < 8; ++it) {
            int i   = tid + it * 128;
            int row = i >> 3;
            int j   = i & 7;
            float4 v = xv[goffs[row][l] + j];
            gs[j * 4 + 0][row] = v.x;
            gs[j * 4 + 1][row] = v.y;
            gs[j * 4 + 2][row] = v.z;
            gs[j * 4 + 3][row] = v.w;
        }
        // Stage W chunk: rows l*32 .. l*32+31, all 64 cols.
#pragma unroll
        for (int it = 0; it < 4; ++it) {
            int i   = tid + it * 128;
            int row = i >> 4;
            int c4  = i & 15;
            ((float4*)&ws[row][0])[c4] = wv[(l * CIN + row) * (CO / 4) + c4];
        }
        __syncthreads();

#pragma unroll 2
        for (int k = 0; k < CIN; ++k) {
            // a values for this k, duplicated into both f32x2 lanes.
            u64 ad[8];
#pragma unroll
            for (int i = 0; i < 8; i++) {
                float a = gs[k][ri + 16 * i];
                DUP2(ad[i], a);
            }
            // W column pairs: two LDS.128, registers reinterpreted as b64 pairs.
            ulonglong2 wq0 = *(const ulonglong2*)&ws[k][c0];
            ulonglong2 wq1 = *(const ulonglong2*)&ws[k][c0 + 4];
            u64 wp0 = wq0.x, wp1 = wq0.y, wp2 = wq1.x, wp3 = wq1.y;
#pragma unroll
            for (int i = 0; i < 8; i++) {
                FMA2(acc[i][0], ad[i], wp0);
                FMA2(acc[i][1], ad[i], wp1);
                FMA2(acc[i][2], ad[i], wp2);
                FMA2(acc[i][3], ad[i], wp3);
            }
        }
    }

    // Epilogue: bias + ELU, store to scratch.
    float bb[8];
#pragma unroll
    for (int j = 0; j < 8; j++) bb[j] = bias[c0 + j];

#pragma unroll
    for (int i = 0; i < 8; i++) {
        int rr = r0 + ri + 16 * i;
        float o[8];
#pragma unroll
        for (int j = 0; j < 4; j++) {
            float lo, hi;
            UNPACK2(lo, hi, acc[i][j]);
            float v0 = lo + bb[2 * j];
            float v1 = hi + bb[2 * j + 1];
            o[2 * j]     = v0 > 0.f ? v0 : expm1f(v0);
            o[2 * j + 1] = v1 > 0.f ? v1 : expm1f(v1);
        }
        float4* dst = (float4*)&g_mid[(size_t)rr * CO + c0];
        dst[0] = make_float4(o[0], o[1], o[2], o[3]);
        dst[1] = make_float4(o[4], o[5], o[6], o[7]);
    }
}

// ---------------------------------------------------------------------------
// Kernel 2: zero the output (harness poisons d_out).
// ---------------------------------------------------------------------------
__global__ void zero_kernel(float4* __restrict__ out)
{
    int i = blockIdx.x * blockDim.x + threadIdx.x;
    out[i] = make_float4(0.f, 0.f, 0.f, 0.f);
}

// ---------------------------------------------------------------------------
// Kernel 3: sparse pooling scatter (coalesced reads + coalesced atomics).
// ---------------------------------------------------------------------------
__global__ void scatter_kernel(const float* __restrict__ values,
                               const int* __restrict__ rows,
                               const int* __restrict__ cols,
                               float* __restrict__ pooled)
{
    int t = blockIdx.x * blockDim.x + threadIdx.x;
    int o = t & 63;
    int b = (t >> 6) & 7;
    int e = t >> 9;
    int col = cols[e];
    int row = rows[e];
    float v = values[e];
    float val = g_mid[((size_t)b * N_ + col) * CO + o];
    atomicAdd(&pooled[((size_t)b * M_ + row) * CO + o], val * v);
}

// ---------------------------------------------------------------------------
// Inputs: 0 x, 1 weight, 2 bias, 3 values, 4 spiral_indices(i32),
//         5 rows(i32), 6 cols(i32), 7 num_out_verts (unused).
// Output: (8, 12500, 64) fp32.
// ---------------------------------------------------------------------------
extern "C" void kernel_launch(void* const* d_in, const int* in_sizes, int n_in,
                              void* d_out, int out_size)
{
    const float* x      = (const float*)d_in[0];
    const float* w      = (const float*)d_in[1];
    const float* bias   = (const float*)d_in[2];
    const float* values = (const float*)d_in[3];
    const int*   sp     = (const int*)d_in[4];
    const int*   rows   = (const int*)d_in[5];
    const int*   cols   = (const int*)d_in[6];
    float*       out    = (float*)d_out;

    spiral_gemm_kernel<<<R_ / TILE_R, 128>>>(x, w, bias, sp);
    zero_kernel<<<(B_ * M_ * CO / 4) / 256, 256>>>((float4*)out);
    scatter_kernel<<<(NNZ_ * 512) / 256, 256>>>(values, rows, cols, out);
}